// round 3
// baseline (speedup 1.0000x reference)
#include <cuda_runtime.h>
#include <cuda_bf16.h>
#include <math.h>
#include <stdint.h>

// Problem constants
#define BQ    8
#define CIN   256
#define COUT  256
#define NPTS  8192
#define LQ    (3 * NPTS)      // 24576 columns per (batch) GEMM
#define MTOT  (2 * COUT)      // 512 rows: [W_feat; W_dir]

// GEMM tiling
#define BM 128
#define BN 128
#define BK 32
#define KEFF 768              // 3 split passes x 256
#define NKC  (KEFF / BK)      // 24 k-chunks

// SMEM: rows of 64B data padded to 80B pitch (conflict-free ldmatrix: (5r+c)%8 perm)
#define ROWP 80
#define TILE_BYTES (128 * ROWP)           // 10240
#define STAGE_BYTES (2 * TILE_BYTES)      // A + B

// ---------------------------------------------------------------------------
// Static device scratch (no runtime allocation)
// ---------------------------------------------------------------------------
__device__ float g_p[(size_t)BQ * COUT * LQ];   // 192 MiB
__device__ float g_d[(size_t)BQ * COUT * LQ];   // 192 MiB
__device__ __nv_bfloat16 g_xhi[(size_t)BQ * LQ * CIN];  // transposed [b, l, k]
__device__ __nv_bfloat16 g_xlo[(size_t)BQ * LQ * CIN];
__device__ __nv_bfloat16 g_whi[MTOT * CIN];
__device__ __nv_bfloat16 g_wlo[MTOT * CIN];
__device__ float g_sum[COUT];
__device__ float g_sumsq[COUT];
__device__ float g_bn_a[COUT];
__device__ float g_bn_b[COUT];

// ---------------------------------------------------------------------------
// PTX helpers (all sm_80-era: valid for plain sm_103 target)
// ---------------------------------------------------------------------------
__device__ __forceinline__ uint32_t smem_u32(const void* p) {
    uint32_t a;
    asm("{ .reg .u64 t; cvta.to.shared.u64 t, %1; cvt.u32.u64 %0, t; }" : "=r"(a) : "l"(p));
    return a;
}

__device__ __forceinline__ void cp16(uint32_t dst, const void* src) {
    asm volatile("cp.async.cg.shared.global [%0], [%1], 16;" :: "r"(dst), "l"(src) : "memory");
}
#define CP_COMMIT() asm volatile("cp.async.commit_group;" ::: "memory")
#define CP_WAIT(n)  asm volatile("cp.async.wait_group %0;" :: "n"(n) : "memory")

__device__ __forceinline__ void ldsm4(uint32_t* r, uint32_t addr) {
    asm volatile("ldmatrix.sync.aligned.m8n8.x4.shared.b16 {%0,%1,%2,%3}, [%4];"
                 : "=r"(r[0]), "=r"(r[1]), "=r"(r[2]), "=r"(r[3]) : "r"(addr));
}

__device__ __forceinline__ void mma16816(float* c, const uint32_t* a,
                                         uint32_t b0, uint32_t b1) {
    asm volatile(
        "mma.sync.aligned.m16n8k16.row.col.f32.bf16.bf16.f32 "
        "{%0,%1,%2,%3}, {%4,%5,%6,%7}, {%8,%9}, {%0,%1,%2,%3};"
        : "+f"(c[0]), "+f"(c[1]), "+f"(c[2]), "+f"(c[3])
        : "r"(a[0]), "r"(a[1]), "r"(a[2]), "r"(a[3]), "r"(b0), "r"(b1));
}

// ---------------------------------------------------------------------------
// K_a: W -> concatenated bf16 hi/lo [512, 256]
// ---------------------------------------------------------------------------
__global__ void convert_w_kernel(const float* __restrict__ Wf, const float* __restrict__ Wd)
{
    int row = blockIdx.x;
    int col = threadIdx.x;
    float v = (row < COUT) ? Wf[row * CIN + col] : Wd[(row - COUT) * CIN + col];
    __nv_bfloat16 hi = __float2bfloat16(v);
    float r = v - __bfloat162float(hi);
    g_whi[row * CIN + col] = hi;
    g_wlo[row * CIN + col] = __float2bfloat16(r);
}

// ---------------------------------------------------------------------------
// K_b: x [b, k, l] fp32 -> Xt_hi/Xt_lo [b, l, k] bf16 (transpose + split)
// ---------------------------------------------------------------------------
__global__ __launch_bounds__(256)
void transpose_split_kernel(const float* __restrict__ x)
{
    __shared__ float s[32][33];
    const int b  = blockIdx.z;
    const int k0 = blockIdx.y * 32;
    const int l0 = blockIdx.x * 32;
    const int tx = threadIdx.x, ty = threadIdx.y;

    const float* xb = x + ((size_t)b * CIN + k0) * LQ + l0;
#pragma unroll
    for (int i = 0; i < 4; i++) {
        int k = ty + i * 8;
        s[k][tx] = xb[(size_t)k * LQ + tx];
    }
    __syncthreads();
#pragma unroll
    for (int i = 0; i < 4; i++) {
        int lr = ty + i * 8;
        float v = s[tx][lr];
        __nv_bfloat16 hi = __float2bfloat16(v);
        float r = v - __bfloat162float(hi);
        size_t off = ((size_t)b * LQ + l0 + lr) * CIN + k0 + tx;
        g_xhi[off] = hi;
        g_xlo[off] = __float2bfloat16(r);
    }
}

// ---------------------------------------------------------------------------
// K1: mma.sync bf16 GEMM  C[512, 24576] (3-pass split) per batch
// grid (4 m, 192 l, 8 b), 256 threads, 8 warps as 4(m) x 2(n)
// ---------------------------------------------------------------------------
__global__ __launch_bounds__(256, 2)
void gemm_mma_kernel()
{
    __shared__ char smem[2 * STAGE_BYTES];    // 40 KB: [stage][A|B]
    const uint32_t su = smem_u32(smem);

    const int tid  = threadIdx.x;
    const int lane = tid & 31;
    const int w    = tid >> 5;
    const int wm   = w >> 1;                  // 0..3 -> 32 m rows each
    const int wn   = w & 1;                   // 0..1 -> 64 l cols each

    const int m0 = blockIdx.x * BM;           // 0,128,256,384 concat rows
    const int l0 = blockIdx.y * BN;
    const int b  = blockIdx.z;
    const size_t blbase = (size_t)b * LQ + l0;

    float acc[2][8][4];
#pragma unroll
    for (int i = 0; i < 2; i++)
#pragma unroll
        for (int j = 0; j < 8; j++)
#pragma unroll
            for (int q = 0; q < 4; q++) acc[i][j][q] = 0.f;

    // per-stage load: A 128x32 bf16 + B 128x32 bf16, 80B row pitch
    const int f0  = tid * 2;                   // this thread's two 16B chunks
    auto load_stage = [&](int st, int kc) {
        const int seg  = kc >> 3;              // 0,1,2
        const int koff = (kc & 7) * BK;
        const __nv_bfloat16* Asrc = (seg < 2) ? g_whi : g_wlo;
        const __nv_bfloat16* Bsrc = (seg == 1) ? g_xlo : g_xhi;
        const uint32_t abase = su + st * STAGE_BYTES;
        const uint32_t bbase = abase + TILE_BYTES;
#pragma unroll
        for (int i = 0; i < 2; i++) {
            int f   = f0 + i;                  // 0..511
            int row = f >> 2;
            int ch  = f & 3;
            cp16(abase + row * ROWP + ch * 16,
                 Asrc + (size_t)(m0 + row) * CIN + koff + ch * 8);
            cp16(bbase + row * ROWP + ch * 16,
                 Bsrc + (blbase + row) * CIN + koff + ch * 8);
        }
        CP_COMMIT();
    };

    load_stage(0, 0);

    const int lrow  = lane & 15;
    const int lhalf = lane >> 4;

    for (int kc = 0; kc < NKC; kc++) {
        const int st = kc & 1;
        if (kc + 1 < NKC) {
            load_stage(st ^ 1, kc + 1);
            CP_WAIT(1);
        } else {
            CP_WAIT(0);
        }
        __syncthreads();

        const uint32_t abase = su + st * STAGE_BYTES;
        const uint32_t bbase = abase + TILE_BYTES;

#pragma unroll
        for (int kk = 0; kk < 2; kk++) {       // two k16 steps in BK=32
            uint32_t a[2][4], bf[4][4];
#pragma unroll
            for (int i = 0; i < 2; i++)
                ldsm4(a[i], abase + (wm * 32 + i * 16 + lrow) * ROWP
                                  + (kk * 16 + lhalf * 8) * 2);
#pragma unroll
            for (int j = 0; j < 4; j++)
                ldsm4(bf[j], bbase + (wn * 64 + j * 16 + lrow) * ROWP
                                   + (kk * 16 + lhalf * 8) * 2);
#pragma unroll
            for (int i = 0; i < 2; i++)
#pragma unroll
                for (int j = 0; j < 4; j++) {
                    mma16816(acc[i][2 * j],     a[i], bf[j][0], bf[j][2]);
                    mma16816(acc[i][2 * j + 1], a[i], bf[j][1], bf[j][3]);
                }
        }
        __syncthreads();
    }

    // Epilogue: fragment -> g_p / g_d
    float* buf = (m0 < COUT) ? g_p : g_d;
#pragma unroll
    for (int i = 0; i < 2; i++) {
        int mrow0 = (m0 & (COUT - 1)) + wm * 32 + i * 16 + (lane >> 2);
#pragma unroll
        for (int j = 0; j < 8; j++) {
            int cg = l0 + wn * 64 + j * 8 + (lane & 3) * 2;
            float2 v0 = make_float2(acc[i][j][0], acc[i][j][1]);
            float2 v1 = make_float2(acc[i][j][2], acc[i][j][3]);
            *reinterpret_cast<float2*>(buf + ((size_t)b * COUT + mrow0) * LQ + cg)       = v0;
            *reinterpret_cast<float2*>(buf + ((size_t)b * COUT + mrow0 + 8) * LQ + cg)   = v1;
        }
    }
}

// ---------------------------------------------------------------------------
// K0: zero stats accumulators
// ---------------------------------------------------------------------------
__global__ void zero_stats_kernel()
{
    int i = threadIdx.x;
    g_sum[i]   = 0.f;
    g_sumsq[i] = 0.f;
}

// ---------------------------------------------------------------------------
// K2: per-channel sum / sumsq of vector norms
// ---------------------------------------------------------------------------
__global__ __launch_bounds__(256)
void stats_kernel()
{
    const int o = blockIdx.x;
    const int b = blockIdx.y;
    const float* base = g_p + ((size_t)b * COUT + o) * LQ;

    float s = 0.f, s2 = 0.f;
    for (int n = threadIdx.x; n < NPTS; n += 256) {
        float px = base[n];
        float py = base[NPTS + n];
        float pz = base[2 * NPTS + n];
        float nrm = sqrtf(px * px + py * py + pz * pz);
        s  += nrm;
        s2 += nrm * nrm;
    }
#pragma unroll
    for (int off = 16; off > 0; off >>= 1) {
        s  += __shfl_down_sync(0xffffffffu, s,  off);
        s2 += __shfl_down_sync(0xffffffffu, s2, off);
    }
    __shared__ float shs[8], shs2[8];
    int wid = threadIdx.x >> 5;
    int lid = threadIdx.x & 31;
    if (lid == 0) { shs[wid] = s; shs2[wid] = s2; }
    __syncthreads();
    if (threadIdx.x == 0) {
        float ts = 0.f, ts2 = 0.f;
#pragma unroll
        for (int w = 0; w < 8; w++) { ts += shs[w]; ts2 += shs2[w]; }
        atomicAdd(&g_sum[o],   ts);
        atomicAdd(&g_sumsq[o], ts2);
    }
}

// ---------------------------------------------------------------------------
// K3: finalize BN affine per channel
// ---------------------------------------------------------------------------
__global__ void finalize_kernel(const float* __restrict__ gamma,
                                const float* __restrict__ beta)
{
    int o = threadIdx.x;
    const float inv = 1.0f / (float)(BQ * NPTS);
    float mean = g_sum[o] * inv;
    float var  = g_sumsq[o] * inv - mean * mean;
    float rstd = rsqrtf(var + 1e-5f);
    float a = rstd * gamma[o];
    g_bn_a[o] = a;
    g_bn_b[o] = beta[o] - mean * a;
}

// ---------------------------------------------------------------------------
// K4: BN rescale + VN LeakyReLU
// ---------------------------------------------------------------------------
__global__ __launch_bounds__(256)
void epilogue_kernel(float* __restrict__ out)
{
    const int n = blockIdx.x * 256 + threadIdx.x;
    const int o = blockIdx.y;
    const int b = blockIdx.z;
    const size_t base = ((size_t)b * COUT + o) * LQ + n;

    float px = g_p[base];
    float py = g_p[base + NPTS];
    float pz = g_p[base + 2 * NPTS];
    float dx = g_d[base];
    float dy = g_d[base + NPTS];
    float dz = g_d[base + 2 * NPTS];

    float nrm = sqrtf(px * px + py * py + pz * pz);
    float f = __ldg(&g_bn_a[o]) + __ldg(&g_bn_b[o]) / nrm;
    px *= f; py *= f; pz *= f;

    float dot = px * dx + py * dy + pz * dz;
    float dsq = dx * dx + dy * dy + dz * dz;
    if (dot < 0.f) {
        float c = 0.8f * dot / (dsq + 1e-6f);
        px -= c * dx; py -= c * dy; pz -= c * dz;
    }
    out[base]            = px;
    out[base + NPTS]     = py;
    out[base + 2 * NPTS] = pz;
}

// ---------------------------------------------------------------------------
extern "C" void kernel_launch(void* const* d_in, const int* in_sizes, int n_in,
                              void* d_out, int out_size)
{
    const float* x     = (const float*)d_in[0];
    const float* Wf    = (const float*)d_in[1];
    const float* Wd    = (const float*)d_in[2];
    const float* gamma = (const float*)d_in[3];
    const float* beta  = (const float*)d_in[4];
    float* out = (float*)d_out;

    convert_w_kernel<<<MTOT, CIN>>>(Wf, Wd);

    dim3 tgrid(LQ / 32, CIN / 32, BQ);
    transpose_split_kernel<<<tgrid, dim3(32, 8)>>>(x);

    dim3 ggrid(MTOT / BM, LQ / BN, BQ);       // (4, 192, 8)
    gemm_mma_kernel<<<ggrid, 256>>>();

    zero_stats_kernel<<<1, COUT>>>();
    stats_kernel<<<dim3(COUT, BQ), 256>>>();
    finalize_kernel<<<1, COUT>>>(gamma, beta);
    epilogue_kernel<<<dim3(NPTS / 256, COUT, BQ), 256>>>(out);
}

// round 4
// speedup vs baseline: 1.4824x; 1.4824x over previous
#include <cuda_runtime.h>
#include <cuda_bf16.h>
#include <math.h>
#include <stdint.h>

// Problem constants
#define BQ    8
#define CIN   256
#define COUT  256
#define NPTS  8192
#define LQ    (3 * NPTS)      // 24576 columns per (batch) GEMM
#define MTOT  (2 * COUT)      // 512 rows: [W_feat; W_dir]

// GEMM tiling
#define BM 128
#define BN 128
#define BK 32
#define KEFF 768              // 3 split passes x 256
#define NKC  (KEFF / BK)      // 24 k-chunks
#define NSTAGE 4

// SMEM: rows of 64B data padded to 80B pitch (conflict-free ldmatrix)
#define ROWP 80
#define TILE_BYTES (128 * ROWP)           // 10240
#define STAGE_BYTES (2 * TILE_BYTES)      // A + B = 20480
#define SMEM_TOTAL (NSTAGE * STAGE_BYTES) // 81920

// ---------------------------------------------------------------------------
// Static device scratch (no runtime allocation)
// ---------------------------------------------------------------------------
__device__ float g_p[(size_t)BQ * COUT * LQ];   // 192 MiB
__device__ float g_d[(size_t)BQ * COUT * LQ];   // 192 MiB
__device__ __nv_bfloat16 g_xhi[(size_t)BQ * LQ * CIN];  // transposed [b, l, k]
__device__ __nv_bfloat16 g_xlo[(size_t)BQ * LQ * CIN];
__device__ __nv_bfloat16 g_whi[MTOT * CIN];
__device__ __nv_bfloat16 g_wlo[MTOT * CIN];
__device__ float g_sum[COUT];
__device__ float g_sumsq[COUT];
__device__ float g_bn_a[COUT];
__device__ float g_bn_b[COUT];

// ---------------------------------------------------------------------------
// PTX helpers (sm_80-era: valid for plain sm_103 target)
// ---------------------------------------------------------------------------
__device__ __forceinline__ uint32_t smem_u32(const void* p) {
    uint32_t a;
    asm("{ .reg .u64 t; cvta.to.shared.u64 t, %1; cvt.u32.u64 %0, t; }" : "=r"(a) : "l"(p));
    return a;
}

__device__ __forceinline__ void cp16(uint32_t dst, const void* src) {
    asm volatile("cp.async.cg.shared.global [%0], [%1], 16;" :: "r"(dst), "l"(src) : "memory");
}
#define CP_COMMIT() asm volatile("cp.async.commit_group;" ::: "memory")
#define CP_WAIT(n)  asm volatile("cp.async.wait_group %0;" :: "n"(n) : "memory")

__device__ __forceinline__ void ldsm4(uint32_t* r, uint32_t addr) {
    asm volatile("ldmatrix.sync.aligned.m8n8.x4.shared.b16 {%0,%1,%2,%3}, [%4];"
                 : "=r"(r[0]), "=r"(r[1]), "=r"(r[2]), "=r"(r[3]) : "r"(addr));
}

__device__ __forceinline__ void mma16816(float* c, const uint32_t* a,
                                         uint32_t b0, uint32_t b1) {
    asm volatile(
        "mma.sync.aligned.m16n8k16.row.col.f32.bf16.bf16.f32 "
        "{%0,%1,%2,%3}, {%4,%5,%6,%7}, {%8,%9}, {%0,%1,%2,%3};"
        : "+f"(c[0]), "+f"(c[1]), "+f"(c[2]), "+f"(c[3])
        : "r"(a[0]), "r"(a[1]), "r"(a[2]), "r"(a[3]), "r"(b0), "r"(b1));
}

// ---------------------------------------------------------------------------
// K_a: W -> concatenated bf16 hi/lo [512, 256]
// ---------------------------------------------------------------------------
__global__ void convert_w_kernel(const float* __restrict__ Wf, const float* __restrict__ Wd)
{
    int row = blockIdx.x;
    int col = threadIdx.x;
    float v = (row < COUT) ? Wf[row * CIN + col] : Wd[(row - COUT) * CIN + col];
    __nv_bfloat16 hi = __float2bfloat16(v);
    float r = v - __bfloat162float(hi);
    g_whi[row * CIN + col] = hi;
    g_wlo[row * CIN + col] = __float2bfloat16(r);
}

// ---------------------------------------------------------------------------
// K_b: x [b, k, l] fp32 -> Xt_hi/Xt_lo [b, l, k] bf16 (transpose + split)
// ---------------------------------------------------------------------------
__global__ __launch_bounds__(256)
void transpose_split_kernel(const float* __restrict__ x)
{
    __shared__ float s[32][33];
    const int b  = blockIdx.z;
    const int k0 = blockIdx.y * 32;
    const int l0 = blockIdx.x * 32;
    const int tx = threadIdx.x, ty = threadIdx.y;

    const float* xb = x + ((size_t)b * CIN + k0) * LQ + l0;
#pragma unroll
    for (int i = 0; i < 4; i++) {
        int k = ty + i * 8;
        s[k][tx] = xb[(size_t)k * LQ + tx];
    }
    __syncthreads();
#pragma unroll
    for (int i = 0; i < 4; i++) {
        int lr = ty + i * 8;
        float v = s[tx][lr];
        __nv_bfloat16 hi = __float2bfloat16(v);
        float r = v - __bfloat162float(hi);
        size_t off = ((size_t)b * LQ + l0 + lr) * CIN + k0 + tx;
        g_xhi[off] = hi;
        g_xlo[off] = __float2bfloat16(r);
    }
}

// ---------------------------------------------------------------------------
// K1: mma.sync bf16 GEMM  C[512, 24576] (3-pass split) per batch
// grid (4 m, 192 l, 8 b), 256 threads, 8 warps as 4(m) x 2(n)
// 4-stage cp.async pipeline, single syncthreads per chunk
// ---------------------------------------------------------------------------
__global__ __launch_bounds__(256, 2)
void gemm_mma_kernel()
{
    extern __shared__ char smem[];            // NSTAGE * STAGE_BYTES
    const uint32_t su = smem_u32(smem);

    const int tid  = threadIdx.x;
    const int lane = tid & 31;
    const int w    = tid >> 5;
    const int wm   = w >> 1;                  // 0..3 -> 32 m rows each
    const int wn   = w & 1;                   // 0..1 -> 64 l cols each

    const int m0 = blockIdx.x * BM;           // 0,128,256,384 concat rows
    const int l0 = blockIdx.y * BN;
    const int b  = blockIdx.z;
    const size_t blbase = (size_t)b * LQ + l0;

    float acc[2][8][4];
#pragma unroll
    for (int i = 0; i < 2; i++)
#pragma unroll
        for (int j = 0; j < 8; j++)
#pragma unroll
            for (int q = 0; q < 4; q++) acc[i][j][q] = 0.f;

    const int f0 = tid * 2;                   // this thread's two 16B chunks
    auto load_stage = [&](int st, int kc) {
        const int seg  = kc >> 3;             // 0,1,2
        const int koff = (kc & 7) * BK;
        const __nv_bfloat16* Asrc = (seg < 2) ? g_whi : g_wlo;
        const __nv_bfloat16* Bsrc = (seg == 1) ? g_xlo : g_xhi;
        const uint32_t abase = su + st * STAGE_BYTES;
        const uint32_t bbase = abase + TILE_BYTES;
#pragma unroll
        for (int i = 0; i < 2; i++) {
            int f   = f0 + i;                 // 0..511
            int row = f >> 2;
            int ch  = f & 3;
            cp16(abase + row * ROWP + ch * 16,
                 Asrc + (size_t)(m0 + row) * CIN + koff + ch * 8);
            cp16(bbase + row * ROWP + ch * 16,
                 Bsrc + (blbase + row) * CIN + koff + ch * 8);
        }
        CP_COMMIT();
    };

    // Prologue: fill 3 stages
    load_stage(0, 0);
    load_stage(1, 1);
    load_stage(2, 2);

    const int lrow  = lane & 15;
    const int lhalf = lane >> 4;

    for (int kc = 0; kc < NKC; kc++) {
        const int st = kc & (NSTAGE - 1);
        CP_WAIT(2);                            // stage kc arrived
        __syncthreads();                       // + all warps done with stage kc-1
        if (kc + 3 < NKC) load_stage((kc + 3) & (NSTAGE - 1), kc + 3);

        const uint32_t abase = su + st * STAGE_BYTES;
        const uint32_t bbase = abase + TILE_BYTES;

#pragma unroll
        for (int kk = 0; kk < 2; kk++) {       // two k16 steps in BK=32
            uint32_t a[2][4], bf[4][4];
#pragma unroll
            for (int i = 0; i < 2; i++)
                ldsm4(a[i], abase + (wm * 32 + i * 16 + lrow) * ROWP
                                  + (kk * 16 + lhalf * 8) * 2);
#pragma unroll
            for (int j = 0; j < 4; j++)
                ldsm4(bf[j], bbase + (wn * 64 + j * 16 + lrow) * ROWP
                                   + (kk * 16 + lhalf * 8) * 2);
#pragma unroll
            for (int i = 0; i < 2; i++)
#pragma unroll
                for (int j = 0; j < 4; j++) {
                    mma16816(acc[i][2 * j],     a[i], bf[j][0], bf[j][2]);
                    mma16816(acc[i][2 * j + 1], a[i], bf[j][1], bf[j][3]);
                }
        }
    }

    // Epilogue: fragment -> g_p / g_d
    float* buf = (m0 < COUT) ? g_p : g_d;
#pragma unroll
    for (int i = 0; i < 2; i++) {
        int mrow0 = (m0 & (COUT - 1)) + wm * 32 + i * 16 + (lane >> 2);
#pragma unroll
        for (int j = 0; j < 8; j++) {
            int cg = l0 + wn * 64 + j * 8 + (lane & 3) * 2;
            float2 v0 = make_float2(acc[i][j][0], acc[i][j][1]);
            float2 v1 = make_float2(acc[i][j][2], acc[i][j][3]);
            *reinterpret_cast<float2*>(buf + ((size_t)b * COUT + mrow0) * LQ + cg)     = v0;
            *reinterpret_cast<float2*>(buf + ((size_t)b * COUT + mrow0 + 8) * LQ + cg) = v1;
        }
    }
}

// ---------------------------------------------------------------------------
// K0: zero stats accumulators
// ---------------------------------------------------------------------------
__global__ void zero_stats_kernel()
{
    int i = threadIdx.x;
    g_sum[i]   = 0.f;
    g_sumsq[i] = 0.f;
}

// ---------------------------------------------------------------------------
// K2: per-channel sum / sumsq of vector norms
// ---------------------------------------------------------------------------
__global__ __launch_bounds__(256)
void stats_kernel()
{
    const int o = blockIdx.x;
    const int b = blockIdx.y;
    const float* base = g_p + ((size_t)b * COUT + o) * LQ;

    float s = 0.f, s2 = 0.f;
    for (int n = threadIdx.x; n < NPTS; n += 256) {
        float px = base[n];
        float py = base[NPTS + n];
        float pz = base[2 * NPTS + n];
        float nrm = sqrtf(px * px + py * py + pz * pz);
        s  += nrm;
        s2 += nrm * nrm;
    }
#pragma unroll
    for (int off = 16; off > 0; off >>= 1) {
        s  += __shfl_down_sync(0xffffffffu, s,  off);
        s2 += __shfl_down_sync(0xffffffffu, s2, off);
    }
    __shared__ float shs[8], shs2[8];
    int wid = threadIdx.x >> 5;
    int lid = threadIdx.x & 31;
    if (lid == 0) { shs[wid] = s; shs2[wid] = s2; }
    __syncthreads();
    if (threadIdx.x == 0) {
        float ts = 0.f, ts2 = 0.f;
#pragma unroll
        for (int w = 0; w < 8; w++) { ts += shs[w]; ts2 += shs2[w]; }
        atomicAdd(&g_sum[o],   ts);
        atomicAdd(&g_sumsq[o], ts2);
    }
}

// ---------------------------------------------------------------------------
// K3: finalize BN affine per channel
// ---------------------------------------------------------------------------
__global__ void finalize_kernel(const float* __restrict__ gamma,
                                const float* __restrict__ beta)
{
    int o = threadIdx.x;
    const float inv = 1.0f / (float)(BQ * NPTS);
    float mean = g_sum[o] * inv;
    float var  = g_sumsq[o] * inv - mean * mean;
    float rstd = rsqrtf(var + 1e-5f);
    float a = rstd * gamma[o];
    g_bn_a[o] = a;
    g_bn_b[o] = beta[o] - mean * a;
}

// ---------------------------------------------------------------------------
// K4: BN rescale + VN LeakyReLU
// ---------------------------------------------------------------------------
__global__ __launch_bounds__(256)
void epilogue_kernel(float* __restrict__ out)
{
    const int n = blockIdx.x * 256 + threadIdx.x;
    const int o = blockIdx.y;
    const int b = blockIdx.z;
    const size_t base = ((size_t)b * COUT + o) * LQ + n;

    float px = g_p[base];
    float py = g_p[base + NPTS];
    float pz = g_p[base + 2 * NPTS];
    float dx = g_d[base];
    float dy = g_d[base + NPTS];
    float dz = g_d[base + 2 * NPTS];

    float nrm = sqrtf(px * px + py * py + pz * pz);
    float f = __ldg(&g_bn_a[o]) + __ldg(&g_bn_b[o]) / nrm;
    px *= f; py *= f; pz *= f;

    float dot = px * dx + py * dy + pz * dz;
    float dsq = dx * dx + dy * dy + dz * dz;
    if (dot < 0.f) {
        float c = 0.8f * dot / (dsq + 1e-6f);
        px -= c * dx; py -= c * dy; pz -= c * dz;
    }
    out[base]            = px;
    out[base + NPTS]     = py;
    out[base + 2 * NPTS] = pz;
}

// ---------------------------------------------------------------------------
extern "C" void kernel_launch(void* const* d_in, const int* in_sizes, int n_in,
                              void* d_out, int out_size)
{
    const float* x     = (const float*)d_in[0];
    const float* Wf    = (const float*)d_in[1];
    const float* Wd    = (const float*)d_in[2];
    const float* gamma = (const float*)d_in[3];
    const float* beta  = (const float*)d_in[4];
    float* out = (float*)d_out;

    // Idempotent; may no-op during graph capture (already set by the
    // correctness call). Return value intentionally ignored.
    (void)cudaFuncSetAttribute(gemm_mma_kernel,
                               cudaFuncAttributeMaxDynamicSharedMemorySize, SMEM_TOTAL);

    convert_w_kernel<<<MTOT, CIN>>>(Wf, Wd);

    dim3 tgrid(LQ / 32, CIN / 32, BQ);
    transpose_split_kernel<<<tgrid, dim3(32, 8)>>>(x);

    zero_stats_kernel<<<1, COUT>>>();          // moved: makes GEMM launch #4 (ncu target)

    dim3 ggrid(MTOT / BM, LQ / BN, BQ);        // (4, 192, 8)
    gemm_mma_kernel<<<ggrid, 256, SMEM_TOTAL>>>();

    stats_kernel<<<dim3(COUT, BQ), 256>>>();
    finalize_kernel<<<1, COUT>>>(gamma, beta);
    epilogue_kernel<<<dim3(NPTS / 256, COUT, BQ), 256>>>(out);
}